// round 1
// baseline (speedup 1.0000x reference)
#include <cuda_runtime.h>

// MediumLSTM: 2-layer LSTM (I=14, H=64, T=256, B=8192) + FC(64->64 relu)->FC(64->2)
// Fused persistent-time kernel: each CTA owns 32 batch rows, keeps all weights in
// shared memory (fp32, transposed + gate-packed), runs the full T=256 recurrence
// for both layers, then the FC head. Batch elements are packed in pairs into
// fma.rn.f32x2 (Blackwell packed fp32) for 2x FMA throughput with exact fp32 math.

#define T_STEPS 256
#define HID     64
#define IN_F    14
#define BT      32      // batch rows per CTA
#define NP      4       // f32x2 pairs per thread (8 batch rows)
#define PADF    34      // padded float stride of h/x rows
#define PADP    17      // padded pair (ull) stride
#define NTH     256

// shared memory float offsets
#define OFF_WHH0 0
#define OFF_WIH1 16384
#define OFF_WHH1 32768
#define OFF_WIH0 49152
#define OFF_H0   52736
#define OFF_H1   54912
#define OFF_XS   57088
#define SMEM_FLOATS 57564
#define SMEM_BYTES (SMEM_FLOATS * 4)

__device__ __forceinline__ unsigned long long pk(float a, float b) {
    unsigned long long r;
    asm("mov.b64 %0, {%1,%2};" : "=l"(r) : "f"(a), "f"(b));
    return r;
}
__device__ __forceinline__ float2 upk(unsigned long long v) {
    float2 r;
    asm("mov.b64 {%0,%1}, %2;" : "=f"(r.x), "=f"(r.y) : "l"(v));
    return r;
}
__device__ __forceinline__ void fma2(unsigned long long &d, unsigned long long a, unsigned long long b) {
    asm("fma.rn.f32x2 %0, %1, %2, %0;" : "+l"(d) : "l"(a), "l"(b));
}
__device__ __forceinline__ float sigf(float x) { return 1.0f / (1.0f + __expf(-x)); }

// 64-wide hidden GEMM: acc[g][p] += Wp[k][u].g * h[k][pair]
__device__ __forceinline__ void gemm64(const float4* __restrict__ w,
                                       const unsigned long long* __restrict__ hv,
                                       int u, int pb,
                                       unsigned long long* a0, unsigned long long* a1,
                                       unsigned long long* a2, unsigned long long* a3) {
#pragma unroll 8
    for (int k = 0; k < HID; k++) {
        float4 w4 = w[k * 64 + u];
        unsigned long long wi = pk(w4.x, w4.x);
        unsigned long long wf = pk(w4.y, w4.y);
        unsigned long long wg = pk(w4.z, w4.z);
        unsigned long long wo = pk(w4.w, w4.w);
#pragma unroll
        for (int p = 0; p < NP; p++) {
            unsigned long long h2 = hv[k * PADP + pb + p];
            fma2(a0[p], wi, h2);
            fma2(a1[p], wf, h2);
            fma2(a2[p], wg, h2);
            fma2(a3[p], wo, h2);
        }
    }
}

__device__ __forceinline__ void lstm_update(const unsigned long long* a0, const unsigned long long* a1,
                                            const unsigned long long* a2, const unsigned long long* a3,
                                            unsigned long long* cst, float* hn) {
#pragma unroll
    for (int p = 0; p < NP; p++) {
        float2 gi = upk(a0[p]);
        float2 gf = upk(a1[p]);
        float2 gg = upk(a2[p]);
        float2 go = upk(a3[p]);
        float2 cc = upk(cst[p]);
        cc.x = sigf(gf.x) * cc.x + sigf(gi.x) * tanhf(gg.x);
        cc.y = sigf(gf.y) * cc.y + sigf(gi.y) * tanhf(gg.y);
        cst[p] = pk(cc.x, cc.y);
        hn[2 * p]     = sigf(go.x) * tanhf(cc.x);
        hn[2 * p + 1] = sigf(go.y) * tanhf(cc.y);
    }
}

__global__ void __launch_bounds__(NTH, 1)
lstm_fused_kernel(const float* __restrict__ x,
                  const float* __restrict__ w_ih0, const float* __restrict__ w_hh0,
                  const float* __restrict__ b_ih0, const float* __restrict__ b_hh0,
                  const float* __restrict__ w_ih1, const float* __restrict__ w_hh1,
                  const float* __restrict__ b_ih1, const float* __restrict__ b_hh1,
                  const float* __restrict__ w_fc1, const float* __restrict__ b_fc1,
                  const float* __restrict__ w_fc2, const float* __restrict__ b_fc2,
                  float* __restrict__ out) {
    extern __shared__ float sm[];
    const int tid = threadIdx.x;
    const int u  = tid & 63;   // hidden unit owned by this thread
    const int bg = tid >> 6;   // batch group (0..3), 8 rows each
    const int pb = bg * NP;    // pair base within a padded row
    const int b0 = blockIdx.x * BT;

    // ---- load weights, transposed + gate-packed: Wp[k][u] = {W[i],W[f],W[g],W[o]} at col k
    for (int n = tid; n < 256 * 64; n += NTH) {
        int j = n >> 6, k = n & 63;
        int g = j >> 6, uu = j & 63;
        int dst = (k * 64 + uu) * 4 + g;
        sm[OFF_WHH0 + dst] = w_hh0[n];
        sm[OFF_WIH1 + dst] = w_ih1[n];
        sm[OFF_WHH1 + dst] = w_hh1[n];
    }
    for (int n = tid; n < 256 * IN_F; n += NTH) {
        int j = n / IN_F, i = n % IN_F;
        int g = j >> 6, uu = j & 63;
        sm[OFF_WIH0 + (i * 64 + uu) * 4 + g] = w_ih0[n];
    }
    // zero h0/h1 state (contiguous region)
    for (int n = tid; n < 2 * 64 * PADF; n += NTH) sm[OFF_H0 + n] = 0.0f;

    // stage x(t=0) into smem (transposed [i][b], padded)
    if (tid < 224) {
        int n0 = tid * 2;
        int bb0 = n0 / IN_F, ii0 = n0 % IN_F;
        int n1 = n0 + 1;
        int bb1 = n1 / IN_F, ii1 = n1 % IN_F;
        sm[OFF_XS + ii0 * PADF + bb0] = x[(size_t)(b0 + bb0) * T_STEPS * IN_F + ii0];
        sm[OFF_XS + ii1 * PADF + bb1] = x[(size_t)(b0 + bb1) * T_STEPS * IN_F + ii1];
    }

    // biases (per-thread, per-gate), packed once
    unsigned long long bp0[4], bp1[4];
#pragma unroll
    for (int g = 0; g < 4; g++) {
        float v0 = b_ih0[g * 64 + u] + b_hh0[g * 64 + u];
        float v1 = b_ih1[g * 64 + u] + b_hh1[g * 64 + u];
        bp0[g] = pk(v0, v0);
        bp1[g] = pk(v1, v1);
    }
    __syncthreads();

    unsigned long long* h0p = (unsigned long long*)(sm + OFF_H0);
    unsigned long long* h1p = (unsigned long long*)(sm + OFF_H1);
    unsigned long long* xsp = (unsigned long long*)(sm + OFF_XS);
    const float4* wHh0 = (const float4*)(sm + OFF_WHH0);
    const float4* wIh1 = (const float4*)(sm + OFF_WIH1);
    const float4* wHh1 = (const float4*)(sm + OFF_WHH1);
    const float4* wIh0 = (const float4*)(sm + OFF_WIH0);

    unsigned long long c0[NP], c1[NP];
#pragma unroll
    for (int p = 0; p < NP; p++) { c0[p] = 0ull; c1[p] = 0ull; }

    for (int t = 0; t < T_STEPS; t++) {
        // ================= layer 0 =================
        unsigned long long a0[NP], a1[NP], a2[NP], a3[NP];
#pragma unroll
        for (int p = 0; p < NP; p++) { a0[p] = bp0[0]; a1[p] = bp0[1]; a2[p] = bp0[2]; a3[p] = bp0[3]; }

        // prefetch x(t+1) into registers (hidden under the GEMMs)
        float nx0 = 0.0f, nx1 = 0.0f;
        if (t + 1 < T_STEPS && tid < 224) {
            int n0 = tid * 2;
            nx0 = x[(size_t)(b0 + n0 / IN_F) * T_STEPS * IN_F + (size_t)(t + 1) * IN_F + n0 % IN_F];
            int n1 = n0 + 1;
            nx1 = x[(size_t)(b0 + n1 / IN_F) * T_STEPS * IN_F + (size_t)(t + 1) * IN_F + n1 % IN_F];
        }

        // input GEMM (14-wide)
#pragma unroll
        for (int i = 0; i < IN_F; i++) {
            float4 w4 = wIh0[i * 64 + u];
            unsigned long long wi = pk(w4.x, w4.x);
            unsigned long long wf = pk(w4.y, w4.y);
            unsigned long long wg = pk(w4.z, w4.z);
            unsigned long long wo = pk(w4.w, w4.w);
#pragma unroll
            for (int p = 0; p < NP; p++) {
                unsigned long long h2 = xsp[i * PADP + pb + p];
                fma2(a0[p], wi, h2);
                fma2(a1[p], wf, h2);
                fma2(a2[p], wg, h2);
                fma2(a3[p], wo, h2);
            }
        }
        // hidden GEMM layer 0
        gemm64(wHh0, h0p, u, pb, a0, a1, a2, a3);

        float hn[2 * NP];
        lstm_update(a0, a1, a2, a3, c0, hn);

        __syncthreads();   // all reads of old h0 / x done
#pragma unroll
        for (int p = 0; p < NP; p++) h0p[u * PADP + pb + p] = pk(hn[2 * p], hn[2 * p + 1]);
        if (t + 1 < T_STEPS && tid < 224) {
            int n0 = tid * 2;
            sm[OFF_XS + (n0 % IN_F) * PADF + n0 / IN_F] = nx0;
            int n1 = n0 + 1;
            sm[OFF_XS + (n1 % IN_F) * PADF + n1 / IN_F] = nx1;
        }
        __syncthreads();   // new h0 + next x visible

        // ================= layer 1 =================
#pragma unroll
        for (int p = 0; p < NP; p++) { a0[p] = bp1[0]; a1[p] = bp1[1]; a2[p] = bp1[2]; a3[p] = bp1[3]; }
        gemm64(wIh1, h0p, u, pb, a0, a1, a2, a3);   // input = new h0
        gemm64(wHh1, h1p, u, pb, a0, a1, a2, a3);   // recurrent = old h1

        lstm_update(a0, a1, a2, a3, c1, hn);

        __syncthreads();   // all reads of old h1 done
#pragma unroll
        for (int p = 0; p < NP; p++) h1p[u * PADP + pb + p] = pk(hn[2 * p], hn[2 * p + 1]);
        __syncthreads();   // new h1 visible
    }

    // ================= FC head =================
    // z[u][b] = relu(sum_k h1[b][k] * w_fc1[u][k] + b_fc1[u]); reuse h0 buffer as z
    {
        unsigned long long z[NP];
        float bb = b_fc1[u];
#pragma unroll
        for (int p = 0; p < NP; p++) z[p] = pk(bb, bb);
#pragma unroll 8
        for (int k = 0; k < HID; k++) {
            float w = w_fc1[u * HID + k];
            unsigned long long w2 = pk(w, w);
#pragma unroll
            for (int p = 0; p < NP; p++) fma2(z[p], w2, h1p[k * PADP + pb + p]);
        }
#pragma unroll
        for (int p = 0; p < NP; p++) {
            float2 zz = upk(z[p]);
            zz.x = fmaxf(zz.x, 0.0f);
            zz.y = fmaxf(zz.y, 0.0f);
            h0p[u * PADP + pb + p] = pk(zz.x, zz.y);
        }
    }
    __syncthreads();

    // out[b][c] = sum_k z[k][b] * w_fc2[c][k] + b_fc2[c]
    if (tid < 64) {
        int b = tid & 31, c = tid >> 5;
        float acc = b_fc2[c];
#pragma unroll 8
        for (int k = 0; k < HID; k++) acc += sm[OFF_H0 + k * PADF + b] * w_fc2[c * HID + k];
        out[(size_t)(b0 + b) * 2 + c] = acc;
    }
}

extern "C" void kernel_launch(void* const* d_in, const int* in_sizes, int n_in,
                              void* d_out, int out_size) {
    const float* x     = (const float*)d_in[0];
    const float* w_ih0 = (const float*)d_in[1];
    const float* w_hh0 = (const float*)d_in[2];
    const float* b_ih0 = (const float*)d_in[3];
    const float* b_hh0 = (const float*)d_in[4];
    const float* w_ih1 = (const float*)d_in[5];
    const float* w_hh1 = (const float*)d_in[6];
    const float* b_ih1 = (const float*)d_in[7];
    const float* b_hh1 = (const float*)d_in[8];
    const float* w_fc1 = (const float*)d_in[9];
    const float* b_fc1 = (const float*)d_in[10];
    const float* w_fc2 = (const float*)d_in[11];
    const float* b_fc2 = (const float*)d_in[12];
    float* out = (float*)d_out;

    cudaFuncSetAttribute(lstm_fused_kernel,
                         cudaFuncAttributeMaxDynamicSharedMemorySize, SMEM_BYTES);

    dim3 grid(8192 / BT);   // 256 CTAs
    dim3 block(NTH);
    lstm_fused_kernel<<<grid, block, SMEM_BYTES>>>(
        x, w_ih0, w_hh0, b_ih0, b_hh0,
        w_ih1, w_hh1, b_ih1, b_hh1,
        w_fc1, b_fc1, w_fc2, b_fc2, out);
}